// round 1
// baseline (speedup 1.0000x reference)
#include <cuda_runtime.h>
#include <math.h>

#define T_TOK 8192
#define H_DIM 2048
#define I_DIM 1408
#define E_NUM 16
#define TOPK  2
#define NSLOT (T_TOK * TOPK)

#define BM 128
#define BN 64
#define BK 16

// ---------------- scratch (device globals; no runtime allocation) -----------
__device__ float g_h[(size_t)NSLOT * I_DIM];     // 92 MB intermediate h = silu(xW1)*xUp
__device__ int   g_top2[T_TOK * TOPK];
__device__ float g_wts[T_TOK * TOPK];
__device__ int   g_cnt[E_NUM];
__device__ int   g_off[E_NUM + 1];
__device__ int   g_fill[E_NUM];
__device__ int   g_tok[NSLOT];
__device__ float g_slotw[NSLOT];

// ---------------- reset per-launch mutable state -----------------------------
__global__ void reset_kernel() {
    int i = threadIdx.x;
    if (i < E_NUM) { g_cnt[i] = 0; g_fill[i] = 0; }
}

// ---------------- gate: logits -> top2 -> softmax weights --------------------
__global__ void gate_kernel(const float* __restrict__ x, const float* __restrict__ gw) {
    int t   = blockIdx.x;
    int tid = threadIdx.x;  // 256 threads
    float acc[E_NUM];
#pragma unroll
    for (int e = 0; e < E_NUM; e++) acc[e] = 0.f;
    const float* xr = x + (size_t)t * H_DIM;
    for (int k = tid; k < H_DIM; k += 256) {
        float xv = xr[k];
#pragma unroll
        for (int e = 0; e < E_NUM; e++) acc[e] += xv * gw[e * H_DIM + k];
    }
    __shared__ float red[256];
    __shared__ float lg[E_NUM];
    for (int e = 0; e < E_NUM; e++) {
        red[tid] = acc[e];
        __syncthreads();
        for (int s = 128; s > 0; s >>= 1) {
            if (tid < s) red[tid] += red[tid + s];
            __syncthreads();
        }
        if (tid == 0) lg[e] = red[0];
        __syncthreads();
    }
    if (tid == 0) {
        // top-1 / top-2, strict > keeps lowest index on ties (matches lax.top_k)
        int e1 = 0; float l1 = lg[0];
        for (int e = 1; e < E_NUM; e++) if (lg[e] > l1) { l1 = lg[e]; e1 = e; }
        int e2 = -1; float l2 = -INFINITY;
        for (int e = 0; e < E_NUM; e++) if (e != e1 && lg[e] > l2) { l2 = lg[e]; e2 = e; }
        float p2  = expf(l2 - l1);          // softmax over the two selected logits
        float inv = 1.f / (1.f + p2);
        g_top2[t * 2]     = e1;
        g_top2[t * 2 + 1] = e2;
        g_wts[t * 2]      = inv;
        g_wts[t * 2 + 1]  = p2 * inv;
        atomicAdd(&g_cnt[e1], 1);
        atomicAdd(&g_cnt[e2], 1);
    }
}

__global__ void offsets_kernel() {
    if (threadIdx.x == 0) {
        int s = 0;
        for (int e = 0; e < E_NUM; e++) { g_off[e] = s; s += g_cnt[e]; }
        g_off[E_NUM] = s;
    }
}

__global__ void scatter_kernel() {
    int t = blockIdx.x * blockDim.x + threadIdx.x;
    if (t >= T_TOK) return;
#pragma unroll
    for (int kk = 0; kk < TOPK; kk++) {
        int e = g_top2[t * 2 + kk];
        int p = atomicAdd(&g_fill[e], 1);
        int slot = g_off[e] + p;
        g_tok[slot]   = t;
        g_slotw[slot] = g_wts[t * 2 + kk];
    }
}

__global__ void zero_out_kernel(float4* out) {
    int i = blockIdx.x * blockDim.x + threadIdx.x;
    out[i] = make_float4(0.f, 0.f, 0.f, 0.f);
}

// ---------------- GEMM1: h[slot, I] = silu(x W1^T) * (x Up^T) ----------------
// C tile 128x64, K=2048, dual accumulators (W1 and Up share the A tile).
__global__ __launch_bounds__(256, 2)
void gemm1_kernel(const float* __restrict__ x, const float* __restrict__ W1,
                  const float* __restrict__ Up) {
    int e = blockIdx.z;
    int base  = g_off[e];
    int count = g_off[e + 1] - base;
    int m0 = blockIdx.y * BM;
    if (m0 >= count) return;
    int n0 = blockIdx.x * BN;

    __shared__ float As [BK][BM];
    __shared__ float B1s[BK][BN];
    __shared__ float B2s[BK][BN];

    int tid  = threadIdx.x;
    int lrow = tid >> 2;          // 0..63
    int kq   = (tid & 3) * 4;     // 0,4,8,12

    int r0 = m0 + lrow, r1 = m0 + lrow + 64;
    int t0 = (r0 < count) ? g_tok[base + r0] : 0;
    int t1 = (r1 < count) ? g_tok[base + r1] : 0;
    const float* a0p = x + (size_t)t0 * H_DIM + kq;
    const float* a1p = x + (size_t)t1 * H_DIM + kq;
    const float* b1p = W1 + (size_t)e * I_DIM * H_DIM + (size_t)(n0 + lrow) * H_DIM + kq;
    const float* b2p = Up + (size_t)e * I_DIM * H_DIM + (size_t)(n0 + lrow) * H_DIM + kq;

    int tx = tid & 15, ty = tid >> 4;

    float accA[8][4], accU[8][4];
#pragma unroll
    for (int i = 0; i < 8; i++)
#pragma unroll
        for (int j = 0; j < 4; j++) { accA[i][j] = 0.f; accU[i][j] = 0.f; }

    for (int k0 = 0; k0 < H_DIM; k0 += BK) {
        float4 a0 = *(const float4*)(a0p + k0);
        float4 a1 = *(const float4*)(a1p + k0);
        float4 b1 = *(const float4*)(b1p + k0);
        float4 b2 = *(const float4*)(b2p + k0);
        __syncthreads();   // previous iteration's smem reads complete
        As [kq + 0][lrow]      = a0.x; As [kq + 1][lrow]      = a0.y;
        As [kq + 2][lrow]      = a0.z; As [kq + 3][lrow]      = a0.w;
        As [kq + 0][lrow + 64] = a1.x; As [kq + 1][lrow + 64] = a1.y;
        As [kq + 2][lrow + 64] = a1.z; As [kq + 3][lrow + 64] = a1.w;
        B1s[kq + 0][lrow] = b1.x; B1s[kq + 1][lrow] = b1.y;
        B1s[kq + 2][lrow] = b1.z; B1s[kq + 3][lrow] = b1.w;
        B2s[kq + 0][lrow] = b2.x; B2s[kq + 1][lrow] = b2.y;
        B2s[kq + 2][lrow] = b2.z; B2s[kq + 3][lrow] = b2.w;
        __syncthreads();
#pragma unroll
        for (int kk = 0; kk < BK; kk++) {
            float4 av0 = *(const float4*)&As [kk][ty * 8];
            float4 av1 = *(const float4*)&As [kk][ty * 8 + 4];
            float4 bv1 = *(const float4*)&B1s[kk][tx * 4];
            float4 bv2 = *(const float4*)&B2s[kk][tx * 4];
            float a[8]  = {av0.x, av0.y, av0.z, av0.w, av1.x, av1.y, av1.z, av1.w};
            float b1v[4] = {bv1.x, bv1.y, bv1.z, bv1.w};
            float b2v[4] = {bv2.x, bv2.y, bv2.z, bv2.w};
#pragma unroll
            for (int i = 0; i < 8; i++) {
#pragma unroll
                for (int j = 0; j < 4; j++) {
                    accA[i][j] += a[i] * b1v[j];
                    accU[i][j] += a[i] * b2v[j];
                }
            }
        }
    }

#pragma unroll
    for (int i = 0; i < 8; i++) {
        int m = m0 + ty * 8 + i;
        if (m < count) {
            int slot = base + m;
            float4 hv;
            float a;
            a = accA[i][0]; hv.x = (a / (1.f + __expf(-a))) * accU[i][0];
            a = accA[i][1]; hv.y = (a / (1.f + __expf(-a))) * accU[i][1];
            a = accA[i][2]; hv.z = (a / (1.f + __expf(-a))) * accU[i][2];
            a = accA[i][3]; hv.w = (a / (1.f + __expf(-a))) * accU[i][3];
            *(float4*)(g_h + (size_t)slot * I_DIM + n0 + tx * 4) = hv;
        }
    }
}

// ---------------- GEMM2: out[t] += w * (h W2^T) -------------------------------
__global__ __launch_bounds__(256, 2)
void gemm2_kernel(const float* __restrict__ W2, float* __restrict__ out) {
    int e = blockIdx.z;
    int base  = g_off[e];
    int count = g_off[e + 1] - base;
    int m0 = blockIdx.y * BM;
    if (m0 >= count) return;
    int n0 = blockIdx.x * BN;

    __shared__ float As[BK][BM];
    __shared__ float Bs[BK][BN];

    int tid  = threadIdx.x;
    int lrow = tid >> 2;
    int kq   = (tid & 3) * 4;

    int s0 = base + m0 + lrow;       if (s0 > NSLOT - 1) s0 = NSLOT - 1;
    int s1 = base + m0 + lrow + 64;  if (s1 > NSLOT - 1) s1 = NSLOT - 1;
    const float* a0p = g_h + (size_t)s0 * I_DIM + kq;
    const float* a1p = g_h + (size_t)s1 * I_DIM + kq;
    const float* bp  = W2 + (size_t)e * H_DIM * I_DIM + (size_t)(n0 + lrow) * I_DIM + kq;

    int tx = tid & 15, ty = tid >> 4;

    float acc[8][4];
#pragma unroll
    for (int i = 0; i < 8; i++)
#pragma unroll
        for (int j = 0; j < 4; j++) acc[i][j] = 0.f;

    for (int k0 = 0; k0 < I_DIM; k0 += BK) {
        float4 a0 = *(const float4*)(a0p + k0);
        float4 a1 = *(const float4*)(a1p + k0);
        float4 b  = *(const float4*)(bp  + k0);
        __syncthreads();
        As[kq + 0][lrow]      = a0.x; As[kq + 1][lrow]      = a0.y;
        As[kq + 2][lrow]      = a0.z; As[kq + 3][lrow]      = a0.w;
        As[kq + 0][lrow + 64] = a1.x; As[kq + 1][lrow + 64] = a1.y;
        As[kq + 2][lrow + 64] = a1.z; As[kq + 3][lrow + 64] = a1.w;
        Bs[kq + 0][lrow] = b.x; Bs[kq + 1][lrow] = b.y;
        Bs[kq + 2][lrow] = b.z; Bs[kq + 3][lrow] = b.w;
        __syncthreads();
#pragma unroll
        for (int kk = 0; kk < BK; kk++) {
            float4 av0 = *(const float4*)&As[kk][ty * 8];
            float4 av1 = *(const float4*)&As[kk][ty * 8 + 4];
            float4 bv  = *(const float4*)&Bs[kk][tx * 4];
            float a[8]  = {av0.x, av0.y, av0.z, av0.w, av1.x, av1.y, av1.z, av1.w};
            float bvv[4] = {bv.x, bv.y, bv.z, bv.w};
#pragma unroll
            for (int i = 0; i < 8; i++) {
#pragma unroll
                for (int j = 0; j < 4; j++) acc[i][j] += a[i] * bvv[j];
            }
        }
    }

#pragma unroll
    for (int i = 0; i < 8; i++) {
        int m = m0 + ty * 8 + i;
        if (m < count) {
            int slot = base + m;
            int t    = g_tok[slot];
            float w  = g_slotw[slot];
            float* op = out + (size_t)t * H_DIM + n0 + tx * 4;
            // exactly 2 contributions per element -> commutative -> deterministic
            atomicAdd(&op[0], w * acc[i][0]);
            atomicAdd(&op[1], w * acc[i][1]);
            atomicAdd(&op[2], w * acc[i][2]);
            atomicAdd(&op[3], w * acc[i][3]);
        }
    }
}

// ---------------- launch ------------------------------------------------------
extern "C" void kernel_launch(void* const* d_in, const int* in_sizes, int n_in,
                              void* d_out, int out_size) {
    const float* x  = (const float*)d_in[0];
    const float* gw = (const float*)d_in[1];
    const float* W1 = (const float*)d_in[2];
    const float* Up = (const float*)d_in[3];
    const float* W2 = (const float*)d_in[4];
    float* out = (float*)d_out;

    reset_kernel<<<1, 32>>>();
    gate_kernel<<<T_TOK, 256>>>(x, gw);
    offsets_kernel<<<1, 32>>>();
    scatter_kernel<<<(T_TOK + 255) / 256, 256>>>();
    zero_out_kernel<<<(T_TOK * H_DIM / 4) / 256, 256>>>((float4*)out);

    dim3 g1(I_DIM / BN, T_TOK / BM, E_NUM);   // (22, 64, 16)
    gemm1_kernel<<<g1, 256>>>(x, W1, Up);

    dim3 g2(H_DIM / BN, T_TOK / BM, E_NUM);   // (32, 64, 16)
    gemm2_kernel<<<g2, 256>>>(W2, out);
}

// round 3
// speedup vs baseline: 2.7075x; 2.7075x over previous
#include <cuda_runtime.h>
#include <math.h>
#include <stdint.h>

#define T_TOK 8192
#define H_DIM 2048
#define I_DIM 1408
#define E_NUM 16
#define TOPK  2
#define NSLOT (T_TOK * TOPK)

#define BM 128
#define BN 128
#define BK 32
#define SROW 44                       // padded floats per smem row (176B, 16B-aligned)
#define ARR (128 * SROW)              // floats per tile array (5632)

// ----------------------------- device scratch --------------------------------
__device__ float g_xc [(size_t)T_TOK * H_DIM];
__device__ float g_w1c[(size_t)E_NUM * I_DIM * H_DIM];
__device__ float g_upc[(size_t)E_NUM * I_DIM * H_DIM];
__device__ float g_w2c[(size_t)E_NUM * H_DIM * I_DIM];
__device__ float g_h  [(size_t)NSLOT * I_DIM];
__device__ float g_o2 [(size_t)NSLOT * H_DIM];
__device__ int   g_top2[T_TOK * 2];
__device__ float g_wts [T_TOK * 2];
__device__ int   g_cnt [E_NUM];
__device__ int   g_off [E_NUM + 1];
__device__ int   g_fill[E_NUM];
__device__ int   g_tok [NSLOT];
__device__ int   g_slot[T_TOK * 2];

// ----------------------------- helpers ---------------------------------------
__device__ __forceinline__ uint32_t smem_u32(const void* p) {
    uint32_t a;
    asm("{ .reg .u64 t; cvta.to.shared.u64 t, %1; cvt.u32.u64 %0, t; }" : "=r"(a) : "l"(p));
    return a;
}
__device__ __forceinline__ float to_tf32(float x) {
    uint32_t r;
    asm("cvt.rna.tf32.f32 %0, %1;" : "=r"(r) : "f"(x));
    return __uint_as_float(r);
}
__device__ __forceinline__ void cp16(uint32_t dst, const float* src) {
    asm volatile("cp.async.cg.shared.global [%0], [%1], 16;"
                 :: "r"(dst), "l"(__cvta_generic_to_global(src)) : "memory");
}
#define CP_COMMIT() asm volatile("cp.async.commit_group;" ::: "memory")
#define CP_WAIT(n)  asm volatile("cp.async.wait_group %0;" :: "n"(n) : "memory")

// m16n8k8 tf32 mma: d += a * b  (row.col; A 16x8, B col-major 8x8, C fp32)
#define MMA_TF32(d, a, b)                                                      \
    asm volatile("mma.sync.aligned.m16n8k8.row.col.f32.tf32.tf32.f32 "         \
        "{%0,%1,%2,%3}, {%4,%5,%6,%7}, {%8,%9}, {%0,%1,%2,%3};"                \
        : "+f"((d)[0]), "+f"((d)[1]), "+f"((d)[2]), "+f"((d)[3])               \
        : "r"((a)[0]), "r"((a)[1]), "r"((a)[2]), "r"((a)[3]),                  \
          "r"((b)[0]), "r"((b)[1]))

__device__ __forceinline__ float silu_mul(float a, float u) {
    return (a / (1.f + __expf(-a))) * u;
}

// ----------------------------- routing kernels -------------------------------
__global__ void reset_kernel() {
    int i = threadIdx.x;
    if (i < E_NUM) { g_cnt[i] = 0; g_fill[i] = 0; }
}

__global__ void gate_kernel(const float* __restrict__ x, const float* __restrict__ gw) {
    int t = blockIdx.x, tid = threadIdx.x;
    float acc[E_NUM];
#pragma unroll
    for (int e = 0; e < E_NUM; e++) acc[e] = 0.f;
    const float* xr = x + (size_t)t * H_DIM;
    for (int k = tid; k < H_DIM; k += 256) {
        float xv = xr[k];
#pragma unroll
        for (int e = 0; e < E_NUM; e++) acc[e] += xv * gw[e * H_DIM + k];
    }
    __shared__ float red[256];
    __shared__ float lg[E_NUM];
    for (int e = 0; e < E_NUM; e++) {
        red[tid] = acc[e];
        __syncthreads();
        for (int s = 128; s > 0; s >>= 1) {
            if (tid < s) red[tid] += red[tid + s];
            __syncthreads();
        }
        if (tid == 0) lg[e] = red[0];
        __syncthreads();
    }
    if (tid == 0) {
        int e1 = 0; float l1 = lg[0];
        for (int e = 1; e < E_NUM; e++) if (lg[e] > l1) { l1 = lg[e]; e1 = e; }
        int e2 = -1; float l2 = -INFINITY;
        for (int e = 0; e < E_NUM; e++) if (e != e1 && lg[e] > l2) { l2 = lg[e]; e2 = e; }
        float p2  = expf(l2 - l1);
        float inv = 1.f / (1.f + p2);
        g_top2[t * 2] = e1; g_top2[t * 2 + 1] = e2;
        g_wts[t * 2] = inv; g_wts[t * 2 + 1] = p2 * inv;
        atomicAdd(&g_cnt[e1], 1);
        atomicAdd(&g_cnt[e2], 1);
    }
}

__global__ void offsets_kernel() {
    if (threadIdx.x == 0) {
        int s = 0;
        for (int e = 0; e < E_NUM; e++) { g_off[e] = s; s += g_cnt[e]; }
        g_off[E_NUM] = s;
    }
}

__global__ void scatter_kernel() {
    int t = blockIdx.x * blockDim.x + threadIdx.x;
    if (t >= T_TOK) return;
#pragma unroll
    for (int kk = 0; kk < TOPK; kk++) {
        int e = g_top2[t * 2 + kk];
        int p = atomicAdd(&g_fill[e], 1);
        int slot = g_off[e] + p;
        g_tok[slot] = t;
        g_slot[t * 2 + kk] = slot;
    }
}

// ----------------------------- tf32 conversion pre-pass ----------------------
__global__ void cvt_kernel(const float4* __restrict__ src, float4* __restrict__ dst, long n4) {
    long i = blockIdx.x * (long)blockDim.x + threadIdx.x;
    long stride = (long)gridDim.x * blockDim.x;
    for (; i < n4; i += stride) {
        float4 v = src[i];
        v.x = to_tf32(v.x); v.y = to_tf32(v.y);
        v.z = to_tf32(v.z); v.w = to_tf32(v.w);
        dst[i] = v;
    }
}

// ----------------------------- GEMM1 (tf32 mma.sync, dual accum) -------------
// h[slot, I] = tf32( silu(x W1^T) * (x Up^T) ),  C-tile 128x128, K = 2048
__global__ __launch_bounds__(512, 1)
void gemm1_mma() {
    extern __shared__ float sm[];
    const int STG = 3 * ARR;                 // floats per stage (A,B1,B2)

    int e = blockIdx.z;
    int base = g_off[e], count = g_off[e + 1] - base;
    int m0 = blockIdx.y * BM;
    if (m0 >= count) return;
    int n0 = blockIdx.x * BN;

    int tid = threadIdx.x;
    int wid = tid >> 5, lane = tid & 31;
    int warpM = wid >> 2, warpN = wid & 3;   // 4x4 warp grid, 32x32 warp tiles
    int g = lane >> 2, tig = lane & 3;

    // ---- gmem->smem geometry: each thread owns rows r0 and r0+64, one float4
    int r0 = tid >> 3;
    int colf = (tid & 7) * 4;
    int mr0 = m0 + r0;          if (mr0 > count - 1) mr0 = count - 1;
    int mr1 = m0 + r0 + 64;     if (mr1 > count - 1) mr1 = count - 1;
    int t0 = g_tok[base + mr0];
    int t1 = g_tok[base + mr1];
    const float* A0  = g_xc  + (size_t)t0 * H_DIM + colf;
    const float* A1  = g_xc  + (size_t)t1 * H_DIM + colf;
    const float* B1a = g_w1c + ((size_t)e * I_DIM + n0 + r0)      * H_DIM + colf;
    const float* B1b = g_w1c + ((size_t)e * I_DIM + n0 + r0 + 64) * H_DIM + colf;
    const float* B2a = g_upc + ((size_t)e * I_DIM + n0 + r0)      * H_DIM + colf;
    const float* B2b = g_upc + ((size_t)e * I_DIM + n0 + r0 + 64) * H_DIM + colf;

    uint32_t sb = smem_u32(sm);
    uint32_t o0 = (uint32_t)(r0 * SROW + colf) * 4u;
    uint32_t o1 = (uint32_t)((r0 + 64) * SROW + colf) * 4u;

    float accA[2][4][4], accU[2][4][4];
#pragma unroll
    for (int mt = 0; mt < 2; mt++)
#pragma unroll
        for (int nt = 0; nt < 4; nt++)
#pragma unroll
            for (int j = 0; j < 4; j++) { accA[mt][nt][j] = 0.f; accU[mt][nt][j] = 0.f; }

    const int KT = H_DIM / BK;   // 64

#define G1_LOAD(s, kt) do {                                                    \
        uint32_t stgb = sb + (uint32_t)(s) * STG * 4u;                         \
        int ko = (kt) * BK;                                                    \
        cp16(stgb + o0,                A0  + ko);                              \
        cp16(stgb + o1,                A1  + ko);                              \
        cp16(stgb + ARR * 4u + o0,     B1a + ko);                              \
        cp16(stgb + ARR * 4u + o1,     B1b + ko);                              \
        cp16(stgb + 2u * ARR * 4u + o0, B2a + ko);                             \
        cp16(stgb + 2u * ARR * 4u + o1, B2b + ko);                             \
    } while (0)

    G1_LOAD(0, 0); CP_COMMIT();
    G1_LOAD(1, 1); CP_COMMIT();

    for (int kt = 0; kt < KT; kt++) {
        CP_WAIT(1);
        __syncthreads();
        if (kt + 2 < KT) {
            int s2 = (kt + 2) % 3;
            G1_LOAD(s2, kt + 2);
        }
        CP_COMMIT();

        const float* S   = sm + (kt % 3) * STG;
        const float* SA  = S;
        const float* SB1 = S + ARR;
        const float* SB2 = S + 2 * ARR;

#pragma unroll
        for (int ks = 0; ks < 4; ks++) {
            int k = ks * 8;
            uint32_t a[2][4];
#pragma unroll
            for (int mt = 0; mt < 2; mt++) {
                int row = warpM * 32 + mt * 16 + g;
                a[mt][0] = __float_as_uint(SA[row * SROW + k + tig]);
                a[mt][1] = __float_as_uint(SA[(row + 8) * SROW + k + tig]);
                a[mt][2] = __float_as_uint(SA[row * SROW + k + tig + 4]);
                a[mt][3] = __float_as_uint(SA[(row + 8) * SROW + k + tig + 4]);
            }
#pragma unroll
            for (int nt = 0; nt < 4; nt++) {
                int col = warpN * 32 + nt * 8 + g;
                uint32_t b1[2], b2[2];
                b1[0] = __float_as_uint(SB1[col * SROW + k + tig]);
                b1[1] = __float_as_uint(SB1[col * SROW + k + tig + 4]);
                b2[0] = __float_as_uint(SB2[col * SROW + k + tig]);
                b2[1] = __float_as_uint(SB2[col * SROW + k + tig + 4]);
#pragma unroll
                for (int mt = 0; mt < 2; mt++) {
                    MMA_TF32(accA[mt][nt], a[mt], b1);
                    MMA_TF32(accU[mt][nt], a[mt], b2);
                }
            }
        }
    }
#undef G1_LOAD

    // epilogue: silu(accA)*accU -> g_h (tf32-rounded)
#pragma unroll
    for (int mt = 0; mt < 2; mt++) {
#pragma unroll
        for (int nt = 0; nt < 4; nt++) {
            int row = m0 + warpM * 32 + mt * 16 + g;
            int col = n0 + warpN * 32 + nt * 8 + 2 * tig;
            if (row < count) {
                float2 v;
                v.x = to_tf32(silu_mul(accA[mt][nt][0], accU[mt][nt][0]));
                v.y = to_tf32(silu_mul(accA[mt][nt][1], accU[mt][nt][1]));
                *(float2*)(g_h + (size_t)(base + row) * I_DIM + col) = v;
            }
            if (row + 8 < count) {
                float2 v;
                v.x = to_tf32(silu_mul(accA[mt][nt][2], accU[mt][nt][2]));
                v.y = to_tf32(silu_mul(accA[mt][nt][3], accU[mt][nt][3]));
                *(float2*)(g_h + (size_t)(base + row + 8) * I_DIM + col) = v;
            }
        }
    }
}

// ----------------------------- GEMM2 (tf32 mma.sync) -------------------------
// o2[slot, H] = h W2^T,  C-tile 128x128, K = 1408
__global__ __launch_bounds__(512, 1)
void gemm2_mma() {
    extern __shared__ float sm[];
    const int STG = 2 * ARR;

    int e = blockIdx.z;
    int base = g_off[e], count = g_off[e + 1] - base;
    int m0 = blockIdx.y * BM;
    if (m0 >= count) return;
    int n0 = blockIdx.x * BN;

    int tid = threadIdx.x;
    int wid = tid >> 5, lane = tid & 31;
    int warpM = wid >> 2, warpN = wid & 3;
    int g = lane >> 2, tig = lane & 3;

    int r0 = tid >> 3;
    int colf = (tid & 7) * 4;
    int mr0 = m0 + r0;          if (mr0 > count - 1) mr0 = count - 1;
    int mr1 = m0 + r0 + 64;     if (mr1 > count - 1) mr1 = count - 1;
    const float* A0 = g_h   + (size_t)(base + mr0) * I_DIM + colf;
    const float* A1 = g_h   + (size_t)(base + mr1) * I_DIM + colf;
    const float* Ba = g_w2c + ((size_t)e * H_DIM + n0 + r0)      * I_DIM + colf;
    const float* Bb = g_w2c + ((size_t)e * H_DIM + n0 + r0 + 64) * I_DIM + colf;

    uint32_t sb = smem_u32(sm);
    uint32_t o0 = (uint32_t)(r0 * SROW + colf) * 4u;
    uint32_t o1 = (uint32_t)((r0 + 64) * SROW + colf) * 4u;

    float acc[2][4][4];
#pragma unroll
    for (int mt = 0; mt < 2; mt++)
#pragma unroll
        for (int nt = 0; nt < 4; nt++)
#pragma unroll
            for (int j = 0; j < 4; j++) acc[mt][nt][j] = 0.f;

    const int KT = I_DIM / BK;   // 44

#define G2_LOAD(s, kt) do {                                                    \
        uint32_t stgb = sb + (uint32_t)(s) * STG * 4u;                         \
        int ko = (kt) * BK;                                                    \
        cp16(stgb + o0,            A0 + ko);                                   \
        cp16(stgb + o1,            A1 + ko);                                   \
        cp16(stgb + ARR * 4u + o0, Ba + ko);                                   \
        cp16(stgb + ARR * 4u + o1, Bb + ko);                                   \
    } while (0)

    G2_LOAD(0, 0); CP_COMMIT();
    G2_LOAD(1, 1); CP_COMMIT();
    G2_LOAD(2, 2); CP_COMMIT();

    for (int kt = 0; kt < KT; kt++) {
        CP_WAIT(2);
        __syncthreads();
        if (kt + 3 < KT) {
            int s2 = (kt + 3) & 3;
            G2_LOAD(s2, kt + 3);
        }
        CP_COMMIT();

        const float* S  = sm + (kt & 3) * STG;
        const float* SA = S;
        const float* SB = S + ARR;

#pragma unroll
        for (int ks = 0; ks < 4; ks++) {
            int k = ks * 8;
            uint32_t a[2][4];
#pragma unroll
            for (int mt = 0; mt < 2; mt++) {
                int row = warpM * 32 + mt * 16 + g;
                a[mt][0] = __float_as_uint(SA[row * SROW + k + tig]);
                a[mt][1] = __float_as_uint(SA[(row + 8) * SROW + k + tig]);
                a[mt][2] = __float_as_uint(SA[row * SROW + k + tig + 4]);
                a[mt][3] = __float_as_uint(SA[(row + 8) * SROW + k + tig + 4]);
            }
#pragma unroll
            for (int nt = 0; nt < 4; nt++) {
                int col = warpN * 32 + nt * 8 + g;
                uint32_t b[2];
                b[0] = __float_as_uint(SB[col * SROW + k + tig]);
                b[1] = __float_as_uint(SB[col * SROW + k + tig + 4]);
#pragma unroll
                for (int mt = 0; mt < 2; mt++) MMA_TF32(acc[mt][nt], a[mt], b);
            }
        }
    }
#undef G2_LOAD

#pragma unroll
    for (int mt = 0; mt < 2; mt++) {
#pragma unroll
        for (int nt = 0; nt < 4; nt++) {
            int row = m0 + warpM * 32 + mt * 16 + g;
            int col = n0 + warpN * 32 + nt * 8 + 2 * tig;
            if (row < count) {
                float2 v = make_float2(acc[mt][nt][0], acc[mt][nt][1]);
                *(float2*)(g_o2 + (size_t)(base + row) * H_DIM + col) = v;
            }
            if (row + 8 < count) {
                float2 v = make_float2(acc[mt][nt][2], acc[mt][nt][3]);
                *(float2*)(g_o2 + (size_t)(base + row + 8) * H_DIM + col) = v;
            }
        }
    }
}

// ----------------------------- combine ---------------------------------------
__global__ void combine_kernel(float4* __restrict__ out) {
    int idx = blockIdx.x * blockDim.x + threadIdx.x;
    int t = idx >> 9;          // H/4 = 512
    int c = idx & 511;
    float w0 = g_wts[t * 2], w1 = g_wts[t * 2 + 1];
    const float4* r0 = (const float4*)(g_o2 + (size_t)g_slot[t * 2]     * H_DIM) + c;
    const float4* r1 = (const float4*)(g_o2 + (size_t)g_slot[t * 2 + 1] * H_DIM) + c;
    float4 a = *r0, b = *r1, v;
    v.x = w0 * a.x + w1 * b.x;
    v.y = w0 * a.y + w1 * b.y;
    v.z = w0 * a.z + w1 * b.z;
    v.w = w0 * a.w + w1 * b.w;
    out[idx] = v;
}

// ----------------------------- launch -----------------------------------------
extern "C" void kernel_launch(void* const* d_in, const int* in_sizes, int n_in,
                              void* d_out, int out_size) {
    const float* x  = (const float*)d_in[0];
    const float* gw = (const float*)d_in[1];
    const float* W1 = (const float*)d_in[2];
    const float* Up = (const float*)d_in[3];
    const float* W2 = (const float*)d_in[4];
    float* out = (float*)d_out;

    const int SMEM1 = 3 * 3 * ARR * 4;   // 202,752 B
    const int SMEM2 = 4 * 2 * ARR * 4;   // 180,224 B
    cudaFuncSetAttribute(gemm1_mma, cudaFuncAttributeMaxDynamicSharedMemorySize, SMEM1);
    cudaFuncSetAttribute(gemm2_mma, cudaFuncAttributeMaxDynamicSharedMemorySize, SMEM2);

    reset_kernel<<<1, 32>>>();
    gate_kernel<<<T_TOK, 256>>>(x, gw);
    offsets_kernel<<<1, 32>>>();
    scatter_kernel<<<(T_TOK + 255) / 256, 256>>>();

    float* xc;  cudaGetSymbolAddress((void**)&xc,  g_xc);
    float* w1c; cudaGetSymbolAddress((void**)&w1c, g_w1c);
    float* upc; cudaGetSymbolAddress((void**)&upc, g_upc);
    float* w2c; cudaGetSymbolAddress((void**)&w2c, g_w2c);
    long xN4 = (long)T_TOK * H_DIM / 4;
    long wN4 = (long)E_NUM * I_DIM * H_DIM / 4;
    cvt_kernel<<<2048, 256>>>((const float4*)x,  (float4*)xc,  xN4);
    cvt_kernel<<<8192, 256>>>((const float4*)W1, (float4*)w1c, wN4);
    cvt_kernel<<<8192, 256>>>((const float4*)Up, (float4*)upc, wN4);
    cvt_kernel<<<8192, 256>>>((const float4*)W2, (float4*)w2c, wN4);

    dim3 g1(I_DIM / BN, T_TOK / BM, E_NUM);   // (11, 64, 16)
    gemm1_mma<<<g1, 512, SMEM1>>>();

    dim3 g2(H_DIM / BN, T_TOK / BM, E_NUM);   // (16, 64, 16)
    gemm2_mma<<<g2, 512, SMEM2>>>();

    combine_kernel<<<(T_TOK * H_DIM / 4) / 256, 256>>>((float4*)out);
}